// round 4
// baseline (speedup 1.0000x reference)
#include <cuda_runtime.h>
#include <cuda_bf16.h>
#include <cstdint>

// Problem constants
#define BATCH   4
#define SEQL    8192
#define DIM     1024
#define HEADS   8
#define SPAN    32                      // rows per block
#define NSPAN   (SEQL / SPAN)           // 256
#define NBLK    (BATCH * NSPAN)         // 1024
#define THREADS 256
#define LN_EPS  1e-5f

// Scratch
__device__ float g_yend[(size_t)NBLK * DIM];       // per-span local end state
__device__ int   g_sync[NBLK + 1];                 // publish flags + ticket

__device__ __forceinline__ int ld_acquire(const int* p) {
    int v;
    asm volatile("ld.global.acquire.gpu.b32 %0, [%1];" : "=r"(v) : "l"(p));
    return v;
}
__device__ __forceinline__ void st_release(int* p, int v) {
    asm volatile("st.global.release.gpu.b32 [%0], %1;" :: "l"(p), "r"(v));
}

extern "C" __global__ void __launch_bounds__(THREADS, 4)
mhesa_fused(const float* __restrict__ x,
            const float* __restrict__ gamma,
            const float* __restrict__ beta,
            const float* __restrict__ alphas,
            const float* __restrict__ paramD,
            float* __restrict__ out)
{
    __shared__ float2 s_stat[SPAN];
    __shared__ int    s_ticket;

    const int tid  = threadIdx.x;
    const int lane = tid & 31;
    const int w    = tid >> 5;

    // Ticket: scheduling-order (b,c) assignment -> lookback predecessors
    // are already resident; consecutive tickets alternate batches.
    if (tid == 0) s_ticket = atomicAdd(&g_sync[NBLK], 1);
    __syncthreads();
    const int t = s_ticket;
    const int b = t & (BATCH - 1);
    const int c = t >> 2;                            // span index 0..NSPAN-1

    const size_t base = ((size_t)b * SEQL + (size_t)c * SPAN) * DIM;
    const float4* __restrict__ xc = (const float4*)(x + base);
    float4* __restrict__ oc = (float4*)(out + base);

    // -------- Pass 1: stream tile from DRAM, per-row LN stats ---------------
    // Row-major access: warp w reduces rows w*4 .. w*4+3. Tile lands in L1/L2.
    #pragma unroll
    for (int j = 0; j < SPAN / 8; j++) {             // 4 rows per warp
        const int r = w * (SPAN / 8) + j;
        float s = 0.f, ss = 0.f;
        #pragma unroll
        for (int i = 0; i < 8; i++) {
            float4 v = xc[(size_t)r * (DIM / 4) + i * 32 + lane];
            s  += (v.x + v.y) + (v.z + v.w);
            ss += v.x * v.x + v.y * v.y + v.z * v.z + v.w * v.w;
        }
        #pragma unroll
        for (int o = 16; o; o >>= 1) {
            s  += __shfl_xor_sync(0xffffffffu, s,  o);
            ss += __shfl_xor_sync(0xffffffffu, ss, o);
        }
        if (lane == 0) {
            float m   = s * (1.f / DIM);
            float var = ss * (1.f / DIM) - m * m;
            s_stat[r] = make_float2(m, rsqrtf(var + LN_EPS));
        }
    }
    __syncthreads();

    // -------- Pass 2: re-read tile (L1/L2 hot), LN + local EMA, store -------
    const float4 gm = ((const float4*)gamma )[tid];
    const float4 bt = ((const float4*)beta  )[tid];
    const float4 pd = ((const float4*)paramD)[tid];
    const float  alp = alphas[tid >> 5];             // head = tid>>5, warp-uniform
    const float  a   = 1.f / (1.f + expf(-alp));
    const float  dec = 1.f - a;

    float4 y = make_float4(0.f, 0.f, 0.f, 0.f);
    #pragma unroll 4
    for (int l = 0; l < SPAN; l++) {
        float4 v = xc[l * (DIM / 4) + tid];
        const float m  = s_stat[l].x;
        const float rs = s_stat[l].y;
        float4 u;
        u.x = (v.x - m) * rs * gm.x + bt.x;
        u.y = (v.y - m) * rs * gm.y + bt.y;
        u.z = (v.z - m) * rs * gm.z + bt.z;
        u.w = (v.w - m) * rs * gm.w + bt.w;
        y.x = fmaf(dec, y.x, a * u.x);
        y.y = fmaf(dec, y.y, a * u.y);
        y.z = fmaf(dec, y.z, a * u.z);
        y.w = fmaf(dec, y.w, a * u.w);
        float4 r;
        r.x = fmaf(u.x, pd.x, y.x);
        r.y = fmaf(u.y, pd.y, y.y);
        r.z = fmaf(u.z, pd.z, y.z);
        r.w = fmaf(u.w, pd.w, y.w);
        oc[l * (DIM / 4) + tid] = r;                 // local result (pre-fixup)
    }

    // -------- Publish local end-state ---------------------------------------
    {
        float4* ye = (float4*)g_yend + (size_t)(b * NSPAN + c) * (DIM / 4);
        ye[tid] = y;
    }
    __threadfence();
    __syncthreads();
    if (tid == 0) st_release(&g_sync[b * NSPAN + c], 1);

    // -------- Decoupled lookback: accumulate carry-in -----------------------
    float4 carry = make_float4(0.f, 0.f, 0.f, 0.f);
    if (c > 0) {
        float dch = dec;                             // dec^SPAN via 5 squarings
        #pragma unroll
        for (int i = 0; i < 5; i++) dch *= dch;
        float f = 1.f;
        int p = c - 1;
        const float4* yeb = (const float4*)g_yend + (size_t)b * NSPAN * (DIM / 4);
        do {
            if (lane == 0) {
                while (ld_acquire(&g_sync[b * NSPAN + p]) == 0) {}
            }
            __syncwarp();
            float4 v = __ldcg(yeb + (size_t)p * (DIM / 4) + tid);
            carry.x = fmaf(f, v.x, carry.x);
            carry.y = fmaf(f, v.y, carry.y);
            carry.z = fmaf(f, v.z, carry.z);
            carry.w = fmaf(f, v.w, carry.w);
            f *= dch;
            p--;
        } while (p >= 0 && f > 1e-6f);               // warp-uniform loop

        // -------- Fixup: add carry * dec^(l+1), truncated by decay ----------
        float cm = fmaxf(fmaxf(fabsf(carry.x), fabsf(carry.y)),
                         fmaxf(fabsf(carry.z), fabsf(carry.w)));
        #pragma unroll
        for (int o = 16; o; o >>= 1)
            cm = fmaxf(cm, __shfl_xor_sync(0xffffffffu, cm, o));

        float pw = dec;
        for (int l = 0; l < SPAN && pw * cm > 3e-6f; l++) {
            float4 v = oc[l * (DIM / 4) + tid];      // same-thread RAW: ordered
            v.x = fmaf(carry.x, pw, v.x);
            v.y = fmaf(carry.y, pw, v.y);
            v.z = fmaf(carry.z, pw, v.z);
            v.w = fmaf(carry.w, pw, v.w);
            oc[l * (DIM / 4) + tid] = v;
            pw *= dec;
        }
    }
}

extern "C" void kernel_launch(void* const* d_in, const int* in_sizes, int n_in,
                              void* d_out, int out_size)
{
    const float* x      = (const float*)d_in[0];
    const float* gamma  = (const float*)d_in[1];
    const float* beta   = (const float*)d_in[2];
    const float* alphas = (const float*)d_in[3];
    const float* paramD = (const float*)d_in[4];
    float* out = (float*)d_out;

    // Reset flags + ticket (capture-legal stream memset).
    void* sym = nullptr;
    cudaGetSymbolAddress(&sym, g_sync);
    cudaMemsetAsync(sym, 0, sizeof(int) * (NBLK + 1), 0);

    mhesa_fused<<<NBLK, THREADS>>>(x, gamma, beta, alphas, paramD, out);
}

// round 9
// speedup vs baseline: 1.3794x; 1.3794x over previous
#include <cuda_runtime.h>
#include <cuda_bf16.h>
#include <cstdint>

// Problem constants
#define BATCH   4
#define SEQL    8192
#define DIM     1024
#define HEADS   8
#define SPAN    32                      // rows per block
#define GROW    8                       // rows per register group
#define NGROUP  (SPAN / GROW)           // 4
#define NSPAN   (SEQL / SPAN)           // 256
#define NBLK    (BATCH * NSPAN)         // 1024
#define THREADS 256
#define LN_EPS  1e-5f

// Scratch
__device__ float g_yend[(size_t)NBLK * DIM];       // per-span local end state
__device__ int   g_sync[NBLK + 1];                 // publish flags + ticket

__device__ __forceinline__ int ld_acquire(const int* p) {
    int v;
    asm volatile("ld.global.acquire.gpu.b32 %0, [%1];" : "=r"(v) : "l"(p));
    return v;
}
__device__ __forceinline__ void st_release(int* p, int v) {
    asm volatile("st.global.release.gpu.b32 [%0], %1;" :: "l"(p), "r"(v));
}

extern "C" __global__ void __launch_bounds__(THREADS, 2)
mhesa_fused(const float* __restrict__ x,
            const float* __restrict__ gamma,
            const float* __restrict__ beta,
            const float* __restrict__ alphas,
            const float* __restrict__ paramD,
            float* __restrict__ out)
{
    __shared__ float s_s [GROW][THREADS];          // per-row partial sums
    __shared__ float s_ss[GROW][THREADS];          // per-row partial sumsq
    __shared__ float2 s_stat[GROW];                // (mean, rstd) current group
    __shared__ int    s_ticket;

    const int tid  = threadIdx.x;
    const int lane = tid & 31;
    const int w    = tid >> 5;

    // Ticket: scheduling-order (b,c) assignment -> lookback predecessors resident.
    if (tid == 0) s_ticket = atomicAdd(&g_sync[NBLK], 1);
    __syncthreads();
    const int t = s_ticket;
    const int b = t & (BATCH - 1);
    const int c = t >> 2;                          // span index 0..NSPAN-1

    const size_t base = ((size_t)b * SEQL + (size_t)c * SPAN) * DIM;
    const float4* __restrict__ xc = (const float4*)(x + base);
    float4* __restrict__ oc = (float4*)(out + base);

    const float4 gm = ((const float4*)gamma )[tid];
    const float4 bt = ((const float4*)beta  )[tid];
    const float4 pd = ((const float4*)paramD)[tid];
    const float  alp = alphas[tid >> 5];           // head = tid>>5, warp-uniform
    const float  a   = 1.f / (1.f + expf(-alp));
    const float  dec = 1.f - a;

    // Double-buffered register tile: 2 x 8 rows x float4 per thread.
    float4 buf[2][GROW];

    // Prologue: issue loads for group 0.
    #pragma unroll
    for (int j = 0; j < GROW; j++)
        buf[0][j] = xc[j * (DIM / 4) + tid];

    float4 y = make_float4(0.f, 0.f, 0.f, 0.f);

    #pragma unroll
    for (int g = 0; g < NGROUP; g++) {
        const int bi = g & 1;
        // Issue next group's loads (covers reduce+EMA latency below).
        if (g + 1 < NGROUP) {
            #pragma unroll
            for (int j = 0; j < GROW; j++)
                buf[bi ^ 1][j] = xc[((g + 1) * GROW + j) * (DIM / 4) + tid];
        }

        // Per-row partials from register buffer.
        #pragma unroll
        for (int j = 0; j < GROW; j++) {
            float4 v = buf[bi][j];
            s_s [j][tid] = (v.x + v.y) + (v.z + v.w);
            s_ss[j][tid] = v.x * v.x + v.y * v.y + v.z * v.z + v.w * v.w;
        }
        __syncthreads();                           // partials ready; prev stats free

        // Warp w reduces row w (GROW == warps == 8).
        {
            float s = 0.f, ss = 0.f;
            #pragma unroll
            for (int k = 0; k < THREADS / 32; k++) {
                s  += s_s [w][lane + 32 * k];
                ss += s_ss[w][lane + 32 * k];
            }
            #pragma unroll
            for (int o = 16; o; o >>= 1) {
                s  += __shfl_xor_sync(0xffffffffu, s,  o);
                ss += __shfl_xor_sync(0xffffffffu, ss, o);
            }
            if (lane == 0) {
                float m   = s * (1.f / DIM);
                float var = ss * (1.f / DIM) - m * m;
                s_stat[w] = make_float2(m, rsqrtf(var + LN_EPS));
            }
        }
        __syncthreads();                           // stats ready

        // LN + EMA + store straight from registers.
        #pragma unroll
        for (int j = 0; j < GROW; j++) {
            float4 v = buf[bi][j];
            const float m  = s_stat[j].x;
            const float rs = s_stat[j].y;
            float4 u;
            u.x = (v.x - m) * rs * gm.x + bt.x;
            u.y = (v.y - m) * rs * gm.y + bt.y;
            u.z = (v.z - m) * rs * gm.z + bt.z;
            u.w = (v.w - m) * rs * gm.w + bt.w;
            y.x = fmaf(dec, y.x, a * u.x);
            y.y = fmaf(dec, y.y, a * u.y);
            y.z = fmaf(dec, y.z, a * u.z);
            y.w = fmaf(dec, y.w, a * u.w);
            float4 r;
            r.x = fmaf(u.x, pd.x, y.x);
            r.y = fmaf(u.y, pd.y, y.y);
            r.z = fmaf(u.z, pd.z, y.z);
            r.w = fmaf(u.w, pd.w, y.w);
            oc[(g * GROW + j) * (DIM / 4) + tid] = r;   // local result (pre-fixup)
        }
    }

    // -------- Publish local end-state ---------------------------------------
    {
        float4* ye = (float4*)g_yend + (size_t)(b * NSPAN + c) * (DIM / 4);
        ye[tid] = y;
    }
    __threadfence();
    __syncthreads();
    if (tid == 0) st_release(&g_sync[b * NSPAN + c], 1);

    // -------- Decoupled lookback: accumulate carry-in -----------------------
    float4 carry = make_float4(0.f, 0.f, 0.f, 0.f);
    if (c > 0) {
        float dch = dec;                           // dec^SPAN via 5 squarings
        #pragma unroll
        for (int i = 0; i < 5; i++) dch *= dch;
        float f = 1.f;
        int p = c - 1;
        const float4* yeb = (const float4*)g_yend + (size_t)b * NSPAN * (DIM / 4);
        do {
            if (lane == 0) {
                while (ld_acquire(&g_sync[b * NSPAN + p]) == 0) {}
            }
            __syncwarp();
            float4 v = __ldcg(yeb + (size_t)p * (DIM / 4) + tid);
            carry.x = fmaf(f, v.x, carry.x);
            carry.y = fmaf(f, v.y, carry.y);
            carry.z = fmaf(f, v.z, carry.z);
            carry.w = fmaf(f, v.w, carry.w);
            f *= dch;
            p--;
        } while (p >= 0 && f > 1e-6f);             // warp-uniform loop

        // -------- Fixup: add carry * dec^(l+1), truncated by decay ----------
        float cm = fmaxf(fmaxf(fabsf(carry.x), fabsf(carry.y)),
                         fmaxf(fabsf(carry.z), fabsf(carry.w)));
        #pragma unroll
        for (int o = 16; o; o >>= 1)
            cm = fmaxf(cm, __shfl_xor_sync(0xffffffffu, cm, o));

        float pw = dec;
        for (int l = 0; l < SPAN && pw * cm > 3e-6f; l++) {
            float4 v = oc[l * (DIM / 4) + tid];    // same-thread RAW: ordered
            v.x = fmaf(carry.x, pw, v.x);
            v.y = fmaf(carry.y, pw, v.y);
            v.z = fmaf(carry.z, pw, v.z);
            v.w = fmaf(carry.w, pw, v.w);
            oc[l * (DIM / 4) + tid] = v;
            pw *= dec;
        }
    }
}

extern "C" void kernel_launch(void* const* d_in, const int* in_sizes, int n_in,
                              void* d_out, int out_size)
{
    const float* x      = (const float*)d_in[0];
    const float* gamma  = (const float*)d_in[1];
    const float* beta   = (const float*)d_in[2];
    const float* alphas = (const float*)d_in[3];
    const float* paramD = (const float*)d_in[4];
    float* out = (float*)d_out;

    // Reset flags + ticket (capture-legal stream memset).
    void* sym = nullptr;
    cudaGetSymbolAddress(&sym, g_sync);
    cudaMemsetAsync(sym, 0, sizeof(int) * (NBLK + 1), 0);

    mhesa_fused<<<NBLK, THREADS>>>(x, gamma, beta, alphas, paramD, out);
}

// round 12
// speedup vs baseline: 1.4062x; 1.0195x over previous
#include <cuda_runtime.h>
#include <cuda_bf16.h>
#include <cstdint>

// Problem constants
#define BATCH   4
#define SEQL    8192
#define DIM     1024
#define HEADS   8
#define SPAN    32                      // rows per block
#define GROW    4                       // rows per register group
#define NGROUP  (SPAN / GROW)           // 8
#define NSPAN   (SEQL / SPAN)           // 256
#define NBLK    (BATCH * NSPAN)         // 1024
#define THREADS 256
#define NWARP   (THREADS / 32)          // 8
#define LN_EPS  1e-5f

// Scratch
__device__ float g_yend[(size_t)NBLK * DIM];       // per-span local end state
__device__ int   g_sync[NBLK * NWARP + 1];         // per-warp flags + ticket (last)

__device__ __forceinline__ int ld_acquire(const int* p) {
    int v;
    asm volatile("ld.global.acquire.gpu.b32 %0, [%1];" : "=r"(v) : "l"(p));
    return v;
}
__device__ __forceinline__ void red_release_add(int* p) {
    asm volatile("red.release.gpu.global.add.s32 [%0], 1;" :: "l"(p) : "memory");
}

extern "C" __global__ void __launch_bounds__(THREADS, 3)
mhesa_fused(const float* __restrict__ x,
            const float* __restrict__ gamma,
            const float* __restrict__ beta,
            const float* __restrict__ alphas,
            const float* __restrict__ paramD,
            float* __restrict__ out)
{
    __shared__ float  s_s [GROW][THREADS];         // per-row partial sums
    __shared__ float  s_ss[GROW][THREADS];         // per-row partial sumsq
    __shared__ float2 s_stat[GROW];                // (mean, rstd) current group
    __shared__ int    s_ticket;

    const int tid  = threadIdx.x;
    const int lane = tid & 31;
    const int w    = tid >> 5;

    // Ticket: scheduling-order (b,c) assignment -> lookback predecessors resident.
    if (tid == 0) s_ticket = atomicAdd(&g_sync[NBLK * NWARP], 1);
    __syncthreads();
    const int t = s_ticket;
    const int b = t & (BATCH - 1);
    const int c = t >> 2;                          // span index 0..NSPAN-1

    const size_t base = ((size_t)b * SEQL + (size_t)c * SPAN) * DIM;
    const float4* __restrict__ xc = (const float4*)(x + base);
    float4* __restrict__ oc = (float4*)(out + base);

    const float4 gm = ((const float4*)gamma )[tid];
    const float4 bt = ((const float4*)beta  )[tid];
    const float4 pd = ((const float4*)paramD)[tid];
    const float  alp = alphas[w];                  // head = tid>>5, warp-uniform
    const float  a   = 1.f / (1.f + expf(-alp));
    const float  dec = 1.f - a;

    // Double-buffered register tile: 2 x 4 rows x float4 per thread.
    float4 buf[2][GROW];

    // Prologue: issue loads for group 0.
    #pragma unroll
    for (int j = 0; j < GROW; j++)
        buf[0][j] = xc[j * (DIM / 4) + tid];

    float4 y = make_float4(0.f, 0.f, 0.f, 0.f);

    #pragma unroll
    for (int g = 0; g < NGROUP; g++) {
        const int bi = g & 1;
        // Issue next group's loads (covers reduce+EMA latency below).
        if (g + 1 < NGROUP) {
            #pragma unroll
            for (int j = 0; j < GROW; j++)
                buf[bi ^ 1][j] = xc[((g + 1) * GROW + j) * (DIM / 4) + tid];
        }

        // Per-row partials from register buffer.
        #pragma unroll
        for (int j = 0; j < GROW; j++) {
            float4 v = buf[bi][j];
            s_s [j][tid] = (v.x + v.y) + (v.z + v.w);
            s_ss[j][tid] = v.x * v.x + v.y * v.y + v.z * v.z + v.w * v.w;
        }
        __syncthreads();                           // partials ready

        // Warps 0..GROW-1 reduce one row each.
        if (w < GROW) {
            float s = 0.f, ss = 0.f;
            #pragma unroll
            for (int k = 0; k < THREADS / 32; k++) {
                s  += s_s [w][lane + 32 * k];
                ss += s_ss[w][lane + 32 * k];
            }
            #pragma unroll
            for (int o = 16; o; o >>= 1) {
                s  += __shfl_xor_sync(0xffffffffu, s,  o);
                ss += __shfl_xor_sync(0xffffffffu, ss, o);
            }
            if (lane == 0) {
                float m   = s * (1.f / DIM);
                float var = ss * (1.f / DIM) - m * m;
                s_stat[w] = make_float2(m, rsqrtf(var + LN_EPS));
            }
        }
        __syncthreads();                           // stats ready

        // LN + EMA + store straight from registers.
        #pragma unroll
        for (int j = 0; j < GROW; j++) {
            float4 v = buf[bi][j];
            const float m  = s_stat[j].x;
            const float rs = s_stat[j].y;
            float4 u;
            u.x = (v.x - m) * rs * gm.x + bt.x;
            u.y = (v.y - m) * rs * gm.y + bt.y;
            u.z = (v.z - m) * rs * gm.z + bt.z;
            u.w = (v.w - m) * rs * gm.w + bt.w;
            y.x = fmaf(dec, y.x, a * u.x);
            y.y = fmaf(dec, y.y, a * u.y);
            y.z = fmaf(dec, y.z, a * u.z);
            y.w = fmaf(dec, y.w, a * u.w);
            float4 r;
            r.x = fmaf(u.x, pd.x, y.x);
            r.y = fmaf(u.y, pd.y, y.y);
            r.z = fmaf(u.z, pd.z, y.z);
            r.w = fmaf(u.w, pd.w, y.w);
            oc[(g * GROW + j) * (DIM / 4) + tid] = r;   // local result (pre-fixup)
        }
    }

    // -------- Per-warp publish: yend store + release counter ----------------
    {
        float4* ye = (float4*)g_yend + (size_t)(b * NSPAN + c) * (DIM / 4);
        ye[tid] = y;                               // each lane's own segment
        red_release_add(&g_sync[(b * NSPAN + c) * NWARP + w]);  // lane's release
    }

    // -------- Decoupled lookback (per warp, no block sync) ------------------
    float4 carry = make_float4(0.f, 0.f, 0.f, 0.f);
    if (c > 0) {
        float dch = dec;                           // dec^SPAN via 5 squarings
        #pragma unroll
        for (int i = 0; i < 5; i++) dch *= dch;
        float f = 1.f;
        int p = c - 1;
        const float4* yeb = (const float4*)g_yend + (size_t)b * NSPAN * (DIM / 4);
        do {
            // All lanes acquire-spin on predecessor's warp-w flag (32 arrivals).
            while (ld_acquire(&g_sync[(b * NSPAN + p) * NWARP + w]) < 32) {}
            float4 v = __ldcg(yeb + (size_t)p * (DIM / 4) + tid);
            carry.x = fmaf(f, v.x, carry.x);
            carry.y = fmaf(f, v.y, carry.y);
            carry.z = fmaf(f, v.z, carry.z);
            carry.w = fmaf(f, v.w, carry.w);
            f *= dch;
            p--;
        } while (p >= 0 && f > 1e-5f);             // warp-uniform loop

        // -------- Fixup: add carry * dec^(l+1), truncated by decay ----------
        float cm = fmaxf(fmaxf(fabsf(carry.x), fabsf(carry.y)),
                         fmaxf(fabsf(carry.z), fabsf(carry.w)));
        #pragma unroll
        for (int o = 16; o; o >>= 1)
            cm = fmaxf(cm, __shfl_xor_sync(0xffffffffu, cm, o));

        float pw = dec;
        for (int l = 0; l < SPAN && pw * cm > 1e-5f; l++) {
            float4 v = oc[l * (DIM / 4) + tid];    // same-thread RAW: ordered
            v.x = fmaf(carry.x, pw, v.x);
            v.y = fmaf(carry.y, pw, v.y);
            v.z = fmaf(carry.z, pw, v.z);
            v.w = fmaf(carry.w, pw, v.w);
            oc[l * (DIM / 4) + tid] = v;
            pw *= dec;
        }
    }
}

extern "C" void kernel_launch(void* const* d_in, const int* in_sizes, int n_in,
                              void* d_out, int out_size)
{
    const float* x      = (const float*)d_in[0];
    const float* gamma  = (const float*)d_in[1];
    const float* beta   = (const float*)d_in[2];
    const float* alphas = (const float*)d_in[3];
    const float* paramD = (const float*)d_in[4];
    float* out = (float*)d_out;

    // Reset flags + ticket (capture-legal stream memset).
    void* sym = nullptr;
    cudaGetSymbolAddress(&sym, g_sync);
    cudaMemsetAsync(sym, 0, sizeof(int) * (NBLK * NWARP + 1), 0);

    mhesa_fused<<<NBLK, THREADS>>>(x, gamma, beta, alphas, paramD, out);
}

// round 13
// speedup vs baseline: 1.4702x; 1.0455x over previous
#include <cuda_runtime.h>
#include <cuda_bf16.h>
#include <cstdint>

// Problem constants
#define BATCH   4
#define SEQL    8192
#define DIM     1024
#define HEADS   8
#define SPAN    16                      // rows per block
#define GROW    4                       // rows per register group
#define NGROUP  (SPAN / GROW)           // 4
#define NSPAN   (SEQL / SPAN)           // 512
#define NBLK    (BATCH * NSPAN)         // 2048
#define THREADS 256
#define NWARP   (THREADS / 32)          // 8
#define LN_EPS  1e-5f

// Scratch
__device__ float g_yend[(size_t)NBLK * DIM];       // per-span local end state
__device__ int   g_sync[NBLK * NWARP + 1];         // per-warp flags + ticket (last)

__device__ __forceinline__ int ld_acquire(const int* p) {
    int v;
    asm volatile("ld.global.acquire.gpu.b32 %0, [%1];" : "=r"(v) : "l"(p));
    return v;
}
__device__ __forceinline__ void red_release_add(int* p) {
    asm volatile("red.release.gpu.global.add.s32 [%0], 1;" :: "l"(p) : "memory");
}

extern "C" __global__ void __launch_bounds__(THREADS, 3)
mhesa_fused(const float* __restrict__ x,
            const float* __restrict__ gamma,
            const float* __restrict__ beta,
            const float* __restrict__ alphas,
            const float* __restrict__ paramD,
            float* __restrict__ out)
{
    extern __shared__ float4 s_r[];                // [SPAN][DIM/4] local results, 64 KB
    __shared__ float  s_s [GROW][THREADS];         // per-row partial sums
    __shared__ float  s_ss[GROW][THREADS];         // per-row partial sumsq
    __shared__ float2 s_stat[GROW];                // (mean, rstd) current group
    __shared__ int    s_ticket;

    const int tid  = threadIdx.x;
    const int lane = tid & 31;
    const int w    = tid >> 5;

    // Ticket: scheduling-order (b,c) assignment -> lookback predecessors resident.
    if (tid == 0) s_ticket = atomicAdd(&g_sync[NBLK * NWARP], 1);
    __syncthreads();
    const int t = s_ticket;
    const int b = t & (BATCH - 1);
    const int c = t >> 2;                          // span index 0..NSPAN-1

    const size_t base = ((size_t)b * SEQL + (size_t)c * SPAN) * DIM;
    const float4* __restrict__ xc = (const float4*)(x + base);
    float4* __restrict__ oc = (float4*)(out + base);

    const float4 gm = ((const float4*)gamma )[tid];
    const float4 bt = ((const float4*)beta  )[tid];
    const float4 pd = ((const float4*)paramD)[tid];
    const float  alp = alphas[w];                  // head = tid>>5, warp-uniform
    const float  a   = 1.f / (1.f + expf(-alp));
    const float  dec = 1.f - a;

    // Double-buffered register tile: 2 x 4 rows x float4 per thread.
    float4 buf[2][GROW];

    // Prologue: issue loads for group 0.
    #pragma unroll
    for (int j = 0; j < GROW; j++)
        buf[0][j] = xc[j * (DIM / 4) + tid];

    float4 y = make_float4(0.f, 0.f, 0.f, 0.f);

    // -------- Stream phase: x -> LN -> EMA -> r into smem (no gmem store) ----
    #pragma unroll
    for (int g = 0; g < NGROUP; g++) {
        const int bi = g & 1;
        // Issue next group's loads (covers reduce+EMA latency below).
        if (g + 1 < NGROUP) {
            #pragma unroll
            for (int j = 0; j < GROW; j++)
                buf[bi ^ 1][j] = xc[((g + 1) * GROW + j) * (DIM / 4) + tid];
        }

        // Per-row partials from register buffer.
        #pragma unroll
        for (int j = 0; j < GROW; j++) {
            float4 v = buf[bi][j];
            s_s [j][tid] = (v.x + v.y) + (v.z + v.w);
            s_ss[j][tid] = v.x * v.x + v.y * v.y + v.z * v.z + v.w * v.w;
        }
        __syncthreads();                           // partials ready

        // Warps 0..GROW-1 reduce one row each.
        if (w < GROW) {
            float s = 0.f, ss = 0.f;
            #pragma unroll
            for (int k = 0; k < THREADS / 32; k++) {
                s  += s_s [w][lane + 32 * k];
                ss += s_ss[w][lane + 32 * k];
            }
            #pragma unroll
            for (int o = 16; o; o >>= 1) {
                s  += __shfl_xor_sync(0xffffffffu, s,  o);
                ss += __shfl_xor_sync(0xffffffffu, ss, o);
            }
            if (lane == 0) {
                float m   = s * (1.f / DIM);
                float var = ss * (1.f / DIM) - m * m;
                s_stat[w] = make_float2(m, rsqrtf(var + LN_EPS));
            }
        }
        __syncthreads();                           // stats ready

        // LN + EMA; stash r = y_local + u*paramD in smem.
        #pragma unroll
        for (int j = 0; j < GROW; j++) {
            float4 v = buf[bi][j];
            const float m  = s_stat[j].x;
            const float rs = s_stat[j].y;
            float4 u;
            u.x = (v.x - m) * rs * gm.x + bt.x;
            u.y = (v.y - m) * rs * gm.y + bt.y;
            u.z = (v.z - m) * rs * gm.z + bt.z;
            u.w = (v.w - m) * rs * gm.w + bt.w;
            y.x = fmaf(dec, y.x, a * u.x);
            y.y = fmaf(dec, y.y, a * u.y);
            y.z = fmaf(dec, y.z, a * u.z);
            y.w = fmaf(dec, y.w, a * u.w);
            float4 r;
            r.x = fmaf(u.x, pd.x, y.x);
            r.y = fmaf(u.y, pd.y, y.y);
            r.z = fmaf(u.z, pd.z, y.z);
            r.w = fmaf(u.w, pd.w, y.w);
            s_r[(g * GROW + j) * (DIM / 4) + tid] = r;
        }
    }

    // -------- Per-warp publish: yend store + release counter ----------------
    {
        float4* ye = (float4*)g_yend + (size_t)(b * NSPAN + c) * (DIM / 4);
        ye[tid] = y;                               // each lane's own segment
        red_release_add(&g_sync[(b * NSPAN + c) * NWARP + w]);  // lane's release
    }

    // -------- Decoupled lookback (per warp, no block sync) ------------------
    float4 carry = make_float4(0.f, 0.f, 0.f, 0.f);
    if (c > 0) {
        float dch = dec;                           // dec^SPAN via 4 squarings
        #pragma unroll
        for (int i = 0; i < 4; i++) dch *= dch;
        float f = 1.f;
        int p = c - 1;
        const float4* yeb = (const float4*)g_yend + (size_t)b * NSPAN * (DIM / 4);
        do {
            // All lanes acquire-spin on predecessor's warp-w flag (32 arrivals).
            while (ld_acquire(&g_sync[(b * NSPAN + p) * NWARP + w]) < 32) {}
            float4 v = __ldcg(yeb + (size_t)p * (DIM / 4) + tid);
            carry.x = fmaf(f, v.x, carry.x);
            carry.y = fmaf(f, v.y, carry.y);
            carry.z = fmaf(f, v.z, carry.z);
            carry.w = fmaf(f, v.w, carry.w);
            f *= dch;
            p--;
        } while (p >= 0 && f > 1e-5f);             // warp-uniform loop
    }

    // -------- Merged store: out = r_smem + carry * dec^(l+1) ----------------
    // LDS pipelines under unroll; single gmem store, no RMW.
    #pragma unroll
    for (int l = 0; l < SPAN; l++) {
        const float pw = dec * __powf(dec, (float)l);   // dec^(l+1), no serial chain
        float4 v = s_r[l * (DIM / 4) + tid];
        v.x = fmaf(carry.x, pw, v.x);
        v.y = fmaf(carry.y, pw, v.y);
        v.z = fmaf(carry.z, pw, v.z);
        v.w = fmaf(carry.w, pw, v.w);
        oc[l * (DIM / 4) + tid] = v;
    }
}

extern "C" void kernel_launch(void* const* d_in, const int* in_sizes, int n_in,
                              void* d_out, int out_size)
{
    const float* x      = (const float*)d_in[0];
    const float* gamma  = (const float*)d_in[1];
    const float* beta   = (const float*)d_in[2];
    const float* alphas = (const float*)d_in[3];
    const float* paramD = (const float*)d_in[4];
    float* out = (float*)d_out;

    // Reset flags + ticket (capture-legal stream memset).
    void* sym = nullptr;
    cudaGetSymbolAddress(&sym, g_sync);
    cudaMemsetAsync(sym, 0, sizeof(int) * (NBLK * NWARP + 1), 0);

    static bool attr_done = false;
    const int smem_bytes = SPAN * DIM * sizeof(float);   // 65536
    if (!attr_done) {
        cudaFuncSetAttribute(mhesa_fused,
                             cudaFuncAttributeMaxDynamicSharedMemorySize, smem_bytes);
        attr_done = true;
    }

    mhesa_fused<<<NBLK, THREADS, smem_bytes>>>(x, gamma, beta, alphas, paramD, out);
}